// round 8
// baseline (speedup 1.0000x reference)
#include <cuda_runtime.h>
#include <cstdint>

// out[t, h] = W[h, seq[t]] + b[h]
// seq: int32 [n_tok], W: fp32 [H, V] row-major, b: fp32 [H], out: fp32 [n_tok, H]
//
// Pipeline (4 launches, R5-proven prologue):
//  1) hist    : bucket counts of v>>3 (one 32B W sector per bucket)
//  2) scan    : exclusive scan -> g_off; re-zeroes g_hist (zero at load ->
//               deterministic across graph replays)
//  3) scatter : counting-sort packed (v,t) int2 pairs by bucket
//  4) gather  : lanes-along-sorted-v, cp.async DOUBLE-BUFFERED chunk pipeline
//               (chunk c+1 loads fire-and-forget into the other smem buffer
//               while chunk c is stored), padded-SMEM transpose, coalesced
//               streaming stores.

#define H_DIM 1024
#define TOK_PER_BLK 32
#define THREADS 256
#define HCHUNK 128
#define NCHUNK (H_DIM / HCHUNK)   // 8
#define SPAD (TOK_PER_BLK + 1)    // 33: conflict-free both phases

#define MAX_N 65536
#define MAX_BUCKETS 8192
#define SCAN_THREADS 1024
#define SCAN_PER 8                 // 1024*8 = 8192 >= MAX_BUCKETS

__device__ int g_hist[MAX_BUCKETS];   // zero at load; scan re-zeroes after use
__device__ int g_off[MAX_BUCKETS];
__device__ int2 g_sorted[MAX_N];      // .x = v, .y = t

// ---------------- sort pipeline (R5-proven) ----------------

__global__ void hist_kernel(const int* __restrict__ seq, int n) {
    int i = blockIdx.x * blockDim.x + threadIdx.x;
    if (i < n) atomicAdd(&g_hist[seq[i] >> 3], 1);
}

__global__ __launch_bounds__(SCAN_THREADS)
void scan_kernel(int nbuckets) {
    __shared__ int warp_sums[32];
    const int tid  = threadIdx.x;
    const int lane = tid & 31;
    const int w    = tid >> 5;

    int vals[SCAN_PER];
    int local = 0;
    #pragma unroll
    for (int i = 0; i < SCAN_PER; i++) {
        int idx = tid * SCAN_PER + i;
        vals[i] = (idx < nbuckets) ? g_hist[idx] : 0;
        local += vals[i];
    }

    int x = local;
    #pragma unroll
    for (int d = 1; d < 32; d <<= 1) {
        int y = __shfl_up_sync(0xFFFFFFFFu, x, d);
        if (lane >= d) x += y;
    }
    if (lane == 31) warp_sums[w] = x;
    __syncthreads();

    if (w == 0) {
        int s = warp_sums[lane];
        #pragma unroll
        for (int d = 1; d < 32; d <<= 1) {
            int y = __shfl_up_sync(0xFFFFFFFFu, s, d);
            if (lane >= d) s += y;
        }
        warp_sums[lane] = s;
    }
    __syncthreads();

    int run = (w > 0 ? warp_sums[w - 1] : 0) + (x - local);
    #pragma unroll
    for (int i = 0; i < SCAN_PER; i++) {
        int idx = tid * SCAN_PER + i;
        if (idx < nbuckets) {
            g_off[idx]  = run;
            g_hist[idx] = 0;         // leave zeroed for next invocation
        }
        run += vals[i];
    }
}

__global__ void scatter_kernel(const int* __restrict__ seq, int n) {
    int t = blockIdx.x * blockDim.x + threadIdx.x;
    if (t < n) {
        int v = seq[t];
        int pos = atomicAdd(&g_off[v >> 3], 1);
        g_sorted[pos] = make_int2(v, t);
    }
}

// ---------------- main gather: cp.async double-buffered ----------------

__device__ __forceinline__ void cp_async4(uint32_t smem_addr, const void* gptr) {
    asm volatile("cp.async.ca.shared.global [%0], [%1], 4;"
                 :: "r"(smem_addr), "l"(gptr));
}
__device__ __forceinline__ void cp_commit() {
    asm volatile("cp.async.commit_group;" ::: "memory");
}
template <int N>
__device__ __forceinline__ void cp_wait() {
    asm volatile("cp.async.wait_group %0;" :: "n"(N) : "memory");
}

__global__ __launch_bounds__(THREADS)
void onehot_gather_pipe_kernel(const float* __restrict__ W,
                               const float* __restrict__ bias,
                               float* __restrict__ out,
                               int n_tok, int V) {
    __shared__ float s_w[2][HCHUNK][SPAD];
    __shared__ int s_t[TOK_PER_BLK];
    __shared__ int s_v[TOK_PER_BLK];

    const int tid  = threadIdx.x;
    const int lane = tid & 31;
    const int w    = tid >> 5;
    const int base = blockIdx.x * TOK_PER_BLK;

    if (tid < TOK_PER_BLK) {
        int j = base + tid;
        int2 vt = (j < n_tok) ? g_sorted[j] : make_int2(0, -1);
        s_v[tid] = vt.x;   // clamped: valid address for padding tokens
        s_t[tid] = vt.y;   // -1 -> skip store
    }
    __syncthreads();

    // Load phase: lane owns token 'lane' (sorted -> few sectors per warp-LDG).
    const int my_v = s_v[lane];
    const float* __restrict__ Wv = W + my_v;

    // Store phase: warp w owns tokens 4w..4w+3.
    int st_t[4];
    #pragma unroll
    for (int q = 0; q < 4; q++) st_t[q] = s_t[(w << 2) + q];

    // smem byte address of s_w[buf][h_local][lane]
    uint32_t s_w_base;
    asm("{ .reg .u64 t; cvta.to.shared.u64 t, %1; cvt.u32.u64 %0, t; }"
        : "=r"(s_w_base) : "l"(&s_w[0][0][0]));

    auto issue_chunk = [&](int c, int buf) {
        const int h_base = c * HCHUNK;
        #pragma unroll
        for (int i = 0; i < 16; i++) {
            int h_local = (i << 3) + w;           // warp w covers w, w+8, ...
            uint32_t dst = s_w_base
                         + (uint32_t)(buf * HCHUNK * SPAD + h_local * SPAD + lane) * 4u;
            cp_async4(dst, Wv + (size_t)(h_base + h_local) * (size_t)V);
        }
        cp_commit();
    };

    issue_chunk(0, 0);

    for (int c = 0; c < NCHUNK; c++) {
        const int h_base = c * HCHUNK;
        const int buf = c & 1;

        // fire-and-forget loads for the NEXT chunk into the other buffer
        if (c + 1 < NCHUNK) issue_chunk(c + 1, (c + 1) & 1);

        // bias for this lane's 4 h positions in the current chunk
        float bl[4];
        #pragma unroll
        for (int hs = 0; hs < 4; hs++)
            bl[hs] = __ldg(bias + h_base + (hs << 5) + lane);

        // wait for chunk c (leave chunk c+1's group in flight), publish to block
        if (c + 1 < NCHUNK) cp_wait<1>(); else cp_wait<0>();
        __syncthreads();

        // ---- store phase: coalesced 128B rows ----
        #pragma unroll
        for (int q = 0; q < 4; q++) {
            const int j = (w << 2) + q;
            const int t = st_t[q];
            if (t < 0) continue;
            float* dst = out + (size_t)t * H_DIM + h_base;
            #pragma unroll
            for (int hs = 0; hs < 4; hs++) {
                int h_local = (hs << 5) + lane;
                float r = s_w[buf][h_local][j] + bl[hs];  // stride-33: conflict-free
                __stcs(dst + h_local, r);
            }
        }
        __syncthreads();  // buf is free to be overwritten at iter c+1's issue
    }
}

// ---------------- launch ----------------

extern "C" void kernel_launch(void* const* d_in, const int* in_sizes, int n_in,
                              void* d_out, int out_size) {
    const int*   seq  = (const int*)d_in[0];
    const float* W    = (const float*)d_in[1];
    const float* bias = (const float*)d_in[2];
    float*       out  = (float*)d_out;

    const int n_tok = in_sizes[0];            // 32768
    const int H     = in_sizes[2];            // 1024
    const int V     = in_sizes[1] / H;        // 50257
    const int nbuckets = (V + 7) >> 3;        // 6283
    (void)out_size; (void)n_in;

    hist_kernel<<<(n_tok + 255) / 256, 256>>>(seq, n_tok);
    scan_kernel<<<1, SCAN_THREADS>>>(nbuckets);
    scatter_kernel<<<(n_tok + 255) / 256, 256>>>(seq, n_tok);

    const int blocks = (n_tok + TOK_PER_BLK - 1) / TOK_PER_BLK;
    onehot_gather_pipe_kernel<<<blocks, THREADS>>>(W, bias, out, n_tok, V);
}

// round 9
// speedup vs baseline: 1.3979x; 1.3979x over previous
#include <cuda_runtime.h>
#include <cstdint>

// out[t, h] = W[h, seq[t]] + b[h]
// seq: int32 [n_tok], W: fp32 [H, V] row-major, b: fp32 [H], out: fp32 [n_tok, H]
//
// Pipeline (4 launches, R5-proven kernel bodies) with PDL overlap:
//  1) hist    : bucket counts of v>>3 (one 32B W sector per bucket)
//  2) scan    : exclusive scan -> g_off; re-zeroes g_hist (zero at load ->
//               deterministic across graph replays).         [PDL launch]
//  3) scatter : counting-sort packed (v,t) int2 by bucket.    [PDL launch]
//               Reads seq BEFORE gridDependencySynchronize -> overlaps.
//  4) gather  : lanes-along-sorted-v loads, padded-SMEM transpose,
//               coalesced streaming stores.                   [PDL launch]
// PDL lets each downstream grid ramp up while the upstream kernel drains;
// cudaGridDependencySynchronize() guards the first dependent read.

#define H_DIM 1024
#define TOK_PER_BLK 32
#define THREADS 256
#define HCHUNK 128
#define NCHUNK (H_DIM / HCHUNK)   // 8

#define MAX_N 65536
#define MAX_BUCKETS 8192
#define SCAN_THREADS 1024
#define SCAN_PER 8                 // 1024*8 = 8192 >= MAX_BUCKETS

__device__ int g_hist[MAX_BUCKETS];   // zero at load; scan re-zeroes after use
__device__ int g_off[MAX_BUCKETS];
__device__ int2 g_sorted[MAX_N];      // .x = v, .y = t

// ---------------- sort pipeline (R5-proven bodies) ----------------

__global__ void hist_kernel(const int* __restrict__ seq, int n) {
    int i = blockIdx.x * blockDim.x + threadIdx.x;
    if (i < n) atomicAdd(&g_hist[seq[i] >> 3], 1);
}

__global__ __launch_bounds__(SCAN_THREADS)
void scan_kernel(int nbuckets) {
    // wait for hist grid before touching g_hist
    cudaGridDependencySynchronize();

    __shared__ int warp_sums[32];
    const int tid  = threadIdx.x;
    const int lane = tid & 31;
    const int w    = tid >> 5;

    int vals[SCAN_PER];
    int local = 0;
    #pragma unroll
    for (int i = 0; i < SCAN_PER; i++) {
        int idx = tid * SCAN_PER + i;
        vals[i] = (idx < nbuckets) ? g_hist[idx] : 0;
        local += vals[i];
    }

    int x = local;
    #pragma unroll
    for (int d = 1; d < 32; d <<= 1) {
        int y = __shfl_up_sync(0xFFFFFFFFu, x, d);
        if (lane >= d) x += y;
    }
    if (lane == 31) warp_sums[w] = x;
    __syncthreads();

    if (w == 0) {
        int s = warp_sums[lane];
        #pragma unroll
        for (int d = 1; d < 32; d <<= 1) {
            int y = __shfl_up_sync(0xFFFFFFFFu, s, d);
            if (lane >= d) s += y;
        }
        warp_sums[lane] = s;
    }
    __syncthreads();

    int run = (w > 0 ? warp_sums[w - 1] : 0) + (x - local);
    #pragma unroll
    for (int i = 0; i < SCAN_PER; i++) {
        int idx = tid * SCAN_PER + i;
        if (idx < nbuckets) {
            g_off[idx]  = run;
            g_hist[idx] = 0;         // leave zeroed for next invocation
        }
        run += vals[i];
    }
}

__global__ void scatter_kernel(const int* __restrict__ seq, int n) {
    int t = blockIdx.x * blockDim.x + threadIdx.x;
    int v = 0;
    if (t < n) v = seq[t];           // independent of scan: do before sync

    cudaGridDependencySynchronize(); // g_off ready after this

    if (t < n) {
        int pos = atomicAdd(&g_off[v >> 3], 1);
        g_sorted[pos] = make_int2(v, t);
    }
}

// ---------------- main gather (R5-proven body) ----------------

__global__ __launch_bounds__(THREADS, 8)
void onehot_gather_xpose_kernel(const float* __restrict__ W,
                                const float* __restrict__ bias,
                                float* __restrict__ out,
                                int n_tok, int V) {
    __shared__ float s_w[HCHUNK][TOK_PER_BLK + 1];  // pad -> conflict-free both phases
    __shared__ int s_t[TOK_PER_BLK];
    __shared__ int s_v[TOK_PER_BLK];

    const int tid  = threadIdx.x;
    const int lane = tid & 31;
    const int w    = tid >> 5;
    const int base = blockIdx.x * TOK_PER_BLK;

    // overlap block ramp with scatter's tail; sync before reading g_sorted
    cudaGridDependencySynchronize();

    if (tid < TOK_PER_BLK) {
        int j = base + tid;
        int2 vt = (j < n_tok) ? g_sorted[j] : make_int2(0, -1);
        s_v[tid] = vt.x;   // clamped: valid address for padding tokens
        s_t[tid] = vt.y;   // -1 -> skip store
    }
    __syncthreads();

    // Load phase: lane owns token 'lane' (sorted values -> few sectors/warp).
    const int my_v = s_v[lane];

    // Store phase: warp w owns tokens 4w..4w+3.
    int st_t[4];
    #pragma unroll
    for (int q = 0; q < 4; q++) st_t[q] = s_t[(w << 2) + q];

    for (int c = 0; c < NCHUNK; c++) {
        const int h_base = c * HCHUNK;

        // ---- load phase: 16 independent gathers per thread ----
        #pragma unroll
        for (int i = 0; i < 16; i++) {
            int h_local = (i << 3) + w;  // warp w covers h_local = w, w+8, ...
            float val = __ldg(W + (size_t)(h_base + h_local) * (size_t)V + my_v);
            s_w[h_local][lane] = val;    // stride-1 across lanes: conflict-free
        }

        // bias for this lane's 4 h positions in the chunk
        float bl[4];
        #pragma unroll
        for (int hs = 0; hs < 4; hs++)
            bl[hs] = __ldg(bias + h_base + (hs << 5) + lane);

        __syncthreads();

        // ---- store phase: coalesced 128B rows ----
        #pragma unroll
        for (int q = 0; q < 4; q++) {
            const int j = (w << 2) + q;
            const int t = st_t[q];
            if (t < 0) continue;
            float* dst = out + (size_t)t * H_DIM + h_base;
            #pragma unroll
            for (int hs = 0; hs < 4; hs++) {
                int h_local = (hs << 5) + lane;
                float r = s_w[h_local][j] + bl[hs];  // stride-33: conflict-free
                __stcs(dst + h_local, r);
            }
        }
        __syncthreads();
    }
}

// ---------------- launch (PDL on the dependency chain) ----------------

template <typename Kern, typename... Args>
static void launch_pdl(Kern k, dim3 grid, dim3 block, Args... args) {
    cudaLaunchConfig_t cfg = {};
    cfg.gridDim  = grid;
    cfg.blockDim = block;
    cfg.dynamicSmemBytes = 0;
    cudaLaunchAttribute attr[1];
    attr[0].id = cudaLaunchAttributeProgrammaticStreamSerialization;
    attr[0].val.programmaticStreamSerializationAllowed = 1;
    cfg.attrs = attr;
    cfg.numAttrs = 1;
    cudaLaunchKernelEx(&cfg, k, args...);
}

extern "C" void kernel_launch(void* const* d_in, const int* in_sizes, int n_in,
                              void* d_out, int out_size) {
    const int*   seq  = (const int*)d_in[0];
    const float* W    = (const float*)d_in[1];
    const float* bias = (const float*)d_in[2];
    float*       out  = (float*)d_out;

    const int n_tok = in_sizes[0];            // 32768
    const int H     = in_sizes[2];            // 1024
    const int V     = in_sizes[1] / H;        // 50257
    const int nbuckets = (V + 7) >> 3;        // 6283
    (void)out_size; (void)n_in;

    hist_kernel<<<(n_tok + 255) / 256, 256>>>(seq, n_tok);

    launch_pdl(scan_kernel, dim3(1), dim3(SCAN_THREADS), nbuckets);
    launch_pdl(scatter_kernel, dim3((n_tok + 255) / 256), dim3(256), seq, n_tok);

    const int blocks = (n_tok + TOK_PER_BLK - 1) / TOK_PER_BLK;
    launch_pdl(onehot_gather_xpose_kernel, dim3(blocks), dim3(THREADS),
               W, bias, out, n_tok, V);
}